// round 16
// baseline (speedup 1.0000x reference)
#include <cuda_runtime.h>
#include <cuda_fp16.h>
#include <math.h>

#define Bb 16
#define Nn 512
#define Dd 96
#define PGRID 592

// ---------------- scratch -------------------------------------------------
__device__ __half g_xh  [(size_t)8192 * 768];
__device__ __half g_wqkv[(size_t)768 * 3072];    // [k][ Wq | Wk | Wv ]
__device__ __half g_woh [(size_t)1536 * 768];
__device__ __half g_ph[256];                     // P'[l][k] hi (k=g, 8..15 zero)
__device__ __half g_pl[256];                     // P'[l][k] lo
__device__ __half g_Qh[(size_t)128 * 512 * 96];
__device__ __half g_Kh[(size_t)128 * 512 * 96];
__device__ __half g_Kl[(size_t)128 * 512 * 96];
__device__ __half g_Vh[(size_t)256 * 512 * 96];
__device__ __half g_S [(size_t)128 * 512 * 512];
__device__ __half g_Ah[(size_t)256 * 512 * 512];
__device__ __half g_Oh[(size_t)8192 * 1536];

// ---------------- helpers --------------------------------------------------
__device__ __forceinline__ unsigned sptr(const void* p) {
    return (unsigned)__cvta_generic_to_shared(p);
}
__device__ __forceinline__ void cpa16(unsigned s, const void* g) {
    asm volatile("cp.async.cg.shared.global [%0], [%1], 16;" :: "r"(s), "l"(g));
}
__device__ __forceinline__ void cpcommit() {
    asm volatile("cp.async.commit_group;");
}
template<int W> __device__ __forceinline__ void cpwait() {
    asm volatile("cp.async.wait_group %0;" :: "n"(W));
}
__device__ __forceinline__ void ldsm4(unsigned f[4], unsigned a) {
    asm volatile("ldmatrix.sync.aligned.m8n8.x4.shared.b16 {%0,%1,%2,%3}, [%4];"
                 : "=r"(f[0]), "=r"(f[1]), "=r"(f[2]), "=r"(f[3]) : "r"(a));
}
__device__ __forceinline__ void ldsm4t(unsigned& r0, unsigned& r1, unsigned& r2,
                                       unsigned& r3, unsigned a) {
    asm volatile("ldmatrix.sync.aligned.m8n8.x4.trans.shared.b16 {%0,%1,%2,%3}, [%4];"
                 : "=r"(r0), "=r"(r1), "=r"(r2), "=r"(r3) : "r"(a));
}
__device__ __forceinline__ void ldsm2t(unsigned& r0, unsigned& r1, unsigned a) {
    asm volatile("ldmatrix.sync.aligned.m8n8.x2.trans.shared.b16 {%0,%1}, [%2];"
                 : "=r"(r0), "=r"(r1) : "r"(a));
}
__device__ __forceinline__ void mmaf16(float c[4], const unsigned a[4],
                                       unsigned b0, unsigned b1) {
    asm volatile(
        "mma.sync.aligned.m16n8k16.row.col.f32.f16.f16.f32 "
        "{%0,%1,%2,%3}, {%4,%5,%6,%7}, {%8,%9}, {%0,%1,%2,%3};"
        : "+f"(c[0]), "+f"(c[1]), "+f"(c[2]), "+f"(c[3])
        : "r"(a[0]), "r"(a[1]), "r"(a[2]), "r"(a[3]), "r"(b0), "r"(b1));
}
__device__ __forceinline__ void hsplit(float v, __half& h, __half& l) {
    h = __float2half_rn(v);
    l = __float2half_rn(v - __half2float(h));
}

// ---------------- fused input split (x, Wq, Wk, Wv, Wout, p) ---------------
__global__ void __launch_bounds__(256) splitAll(
    const float4* __restrict__ x, const float4* __restrict__ Wq,
    const float4* __restrict__ Wk, const float4* __restrict__ Wv,
    const float4* __restrict__ Wout, const float* __restrict__ p)
{
    int i = blockIdx.x * 256 + threadIdx.x;
    if (i < 1572864) {
        float4 v = x[i];
        ((__half2*)g_xh)[i * 2]     = __halves2half2(__float2half_rn(v.x), __float2half_rn(v.y));
        ((__half2*)g_xh)[i * 2 + 1] = __halves2half2(__float2half_rn(v.z), __float2half_rn(v.w));
    } else if (i < 1720320) {
        int j = i - 1572864;
        int row = j / 192, col = (j % 192) * 4;
        float4 v = Wq[j];
        __half2* d = (__half2*)(g_wqkv + (size_t)row * 3072 + col);
        d[0] = __halves2half2(__float2half_rn(v.x), __float2half_rn(v.y));
        d[1] = __halves2half2(__float2half_rn(v.z), __float2half_rn(v.w));
    } else if (i < 1867776) {
        int j = i - 1720320;
        int row = j / 192, col = (j % 192) * 4;
        float4 v = Wk[j];
        __half2* d = (__half2*)(g_wqkv + (size_t)row * 3072 + 768 + col);
        d[0] = __halves2half2(__float2half_rn(v.x), __float2half_rn(v.y));
        d[1] = __halves2half2(__float2half_rn(v.z), __float2half_rn(v.w));
    } else if (i < 2162688) {
        int j = i - 1867776;
        int row = j / 384, col = (j % 384) * 4;
        float4 v = Wv[j];
        __half2* d = (__half2*)(g_wqkv + (size_t)row * 3072 + 1536 + col);
        d[0] = __halves2half2(__float2half_rn(v.x), __float2half_rn(v.y));
        d[1] = __halves2half2(__float2half_rn(v.z), __float2half_rn(v.w));
    } else if (i < 2457600) {
        int j = i - 2162688;
        float4 v = Wout[j];
        ((__half2*)g_woh)[j * 2]     = __halves2half2(__float2half_rn(v.x), __float2half_rn(v.y));
        ((__half2*)g_woh)[j * 2 + 1] = __halves2half2(__float2half_rn(v.z), __float2half_rn(v.w));
    } else if (i < 2457856) {
        int j = i - 2457600;              // 0..255: P'[l][k] transposed split
        int l = j >> 4, k = j & 15;
        float v = (k < 8) ? p[k * 16 + l] : 0.f;
        __half h, lo;
        hsplit(v, h, lo);
        g_ph[j] = h;
        g_pl[j] = lo;
    }
}

// ---------------------------------------------------------------------------
// Persistent GEMM with cross-tile prefetch. BM=128 BN=128 BK=32, 3 stages.
// MODE 0: fp32 rowmajor (outF).  MODE 1: QKV merged epilogue.
// ---------------------------------------------------------------------------
#define ASTR 10240          // 128 rows * 80B
#define BSTR 8704           // 32 rows * 272B

template<int MODE>
__global__ void __launch_bounds__(256, 2) gemm16(
    const __half* __restrict__ Agh, const __half* __restrict__ Bgh,
    const float* __restrict__ bias,
    __half* __restrict__ o0, __half* __restrict__ o1, __half* __restrict__ o2,
    __half* __restrict__ o3, float* __restrict__ outF,
    int K, int N, int tilesX, int nTiles)
{
    extern __shared__ char smem[];
    __half* sA = (__half*)smem;
    __half* sBh = (__half*)(smem + 3 * ASTR);

    const int tid = threadIdx.x;
    const int lane = tid & 31, warp = tid >> 5;
    const int wm = warp >> 2, wn = warp & 3;
    const int gid = lane >> 2, tig = lane & 3;

    const int aR = tid >> 1, aC = (tid & 1) * 16;
    const int bR = tid >> 3, bC = (tid & 7) * 16;
    const unsigned sAb = sptr(sA), sBhb = sptr(sBh);
    const unsigned aOff = (wm * 64 + (lane & 15)) * 80 + (lane >> 4) * 16;
    const unsigned bOff = (lane & 15) * 272 + (wn * 32 + (lane >> 4) * 8) * 2;
    const int KT = K >> 5;

    auto issueT = [&](int t, int kt, int s) {
        const int tm0 = (t / tilesX) * 128;
        const int tn0 = (t % tilesX) * 128;
        const int k0 = kt << 5;
        const __half* ga = Agh + (size_t)(tm0 + aR) * K + k0 + aC;
        unsigned sa = sAb + s * ASTR + aR * 80 + aC * 2;
        cpa16(sa, ga); cpa16(sa + 16, ga + 8);
        const __half* gb = Bgh + (size_t)(k0 + bR) * N + tn0 + bC;
        unsigned sb = sBhb + s * BSTR + bR * 272 + bC * 2;
        cpa16(sb, gb); cpa16(sb + 16, gb + 8);
        cpcommit();
    };

    if (blockIdx.x < nTiles) {
        issueT(blockIdx.x, 0, 0);
        issueT(blockIdx.x, 1, 1);
    }

    for (int tile = blockIdx.x; tile < nTiles; tile += PGRID) {
        const int m0 = (tile / tilesX) * 128;
        const int n0 = (tile % tilesX) * 128;

        float c[4][4][4];
#pragma unroll
        for (int i = 0; i < 4; i++)
#pragma unroll
            for (int j = 0; j < 4; j++)
#pragma unroll
                for (int q = 0; q < 4; q++) c[i][j][q] = 0.f;

        for (int kt = 0; kt < KT; kt++) {
            cpwait<1>();
            __syncthreads();
            const int s = kt % 3;
            const unsigned aB = sAb + s * ASTR + aOff;
            const unsigned bB = sBhb + s * BSTR + bOff;

#pragma unroll
            for (int k16 = 0; k16 < 2; k16++) {
                unsigned ah[4][4], bh[4][2], t0, t1, t2, t3;
#pragma unroll
                for (int mf = 0; mf < 4; mf++)
                    ldsm4(ah[mf], aB + mf * 1280 + k16 * 32);
#pragma unroll
                for (int nf2 = 0; nf2 < 2; nf2++) {
                    ldsm4t(t0, t1, t2, t3, bB + k16 * 4352 + nf2 * 32);
                    bh[nf2 * 2][0] = t0; bh[nf2 * 2][1] = t1;
                    bh[nf2 * 2 + 1][0] = t2; bh[nf2 * 2 + 1][1] = t3;
                }
#pragma unroll
                for (int mf = 0; mf < 4; mf++)
#pragma unroll
                    for (int nf = 0; nf < 4; nf++)
                        mmaf16(c[mf][nf], ah[mf], bh[nf][0], bh[nf][1]);
            }
            const int kn = kt + 2;
            if (kn < KT) issueT(tile, kn, kn % 3); else cpcommit();
        }

        const int nt = tile + PGRID;
        if (nt < nTiles) { issueT(nt, 0, 0); issueT(nt, 1, 1); }

#pragma unroll
        for (int mf = 0; mf < 4; mf++)
#pragma unroll
            for (int q2 = 0; q2 < 2; q2++) {
                const int row = m0 + wm * 64 + mf * 16 + gid + q2 * 8;
                const int b = row >> 9, n = row & 511;
#pragma unroll
                for (int nf = 0; nf < 4; nf++) {
                    const int col = n0 + wn * 32 + nf * 8 + tig * 2;
                    float v0 = c[mf][nf][q2 * 2 + 0];
                    float v1 = c[mf][nf][q2 * 2 + 1];
                    if (MODE == 0) {
                        *(float2*)(outF + (size_t)row * N + col) = make_float2(v0, v1);
                    } else {
                        if (col < 768) {
                            const int h = col / 96, d = col - h * 96;
                            const size_t idx = (((size_t)(b * 8 + h)) * 512 + n) * 96 + d;
                            *(__half2*)(o0 + idx) =
                                __halves2half2(__float2half_rn(v0), __float2half_rn(v1));
                        } else if (col < 1536) {
                            const int cc = col - 768;
                            const int h = cc / 96, d = cc - h * 96;
                            const size_t idx = (((size_t)(b * 8 + h)) * 512 + n) * 96 + d;
                            __half h0, h1, l0, l1;
                            hsplit(v0, h0, l0); hsplit(v1, h1, l1);
                            *(__half2*)(o1 + idx) = __halves2half2(h0, h1);
                            *(__half2*)(o2 + idx) = __halves2half2(l0, l1);
                        } else {
                            const int cc = col - 1536;
                            const int h = cc / 96, d = cc - h * 96;
                            v0 += bias[cc]; v1 += bias[cc + 1];
                            const size_t idx = (((size_t)(b * 16 + h)) * 512 + n) * 96 + d;
                            *(__half2*)(o3 + idx) =
                                __halves2half2(__float2half_rn(v0), __float2half_rn(v1));
                        }
                    }
                }
            }
    }
}

// ---------------------------------------------------------------------------
// Persistent scores with cross-tile prefetch.  Q single, K dual (2-term).
// tiles: 128 bg x 4 x 4 = 2048, KT=3.
// ---------------------------------------------------------------------------
__global__ void __launch_bounds__(256, 2) scores16(
    const float* __restrict__ eps, const float* __restrict__ sigma)
{
    extern __shared__ char smem[];
    __half* sQ  = (__half*)smem;
    __half* sKh = (__half*)(smem + 3 * ASTR);
    __half* sKl = (__half*)(smem + 6 * ASTR);

    const int tid = threadIdx.x;
    const int lane = tid & 31, warp = tid >> 5;
    const int wm = warp >> 2, wn = warp & 3;
    const int gid = lane >> 2, tig = lane & 3;

    const int aR = tid >> 1, aC = (tid & 1) * 16;
    const unsigned bQ = sptr(sQ), bKh = sptr(sKh), bKl = sptr(sKl);
    const unsigned aOff = (wm * 64 + (lane & 15)) * 80 + (lane >> 4) * 16;
    const unsigned kOff = (wn * 32 + (lane & 15)) * 80 + (lane >> 4) * 16;

    auto issueT = [&](int t, int kt, int s) {
        const int tbg = t >> 4;
        const int tsn0 = ((t >> 2) & 3) * 128, tsm0 = (t & 3) * 128;
        const __half* Qp  = g_Qh + (size_t)tbg * Nn * Dd;
        const __half* Khp = g_Kh + (size_t)tbg * Nn * Dd;
        const __half* Klp = g_Kl + (size_t)tbg * Nn * Dd;
        const int k0 = kt << 5;
        unsigned so = s * ASTR + aR * 80 + aC * 2;
        size_t go = (size_t)aR * 96 + k0 + aC;
        cpa16(bQ + so, Qp + (size_t)tsn0 * 96 + go);
        cpa16(bQ + so + 16, Qp + (size_t)tsn0 * 96 + go + 8);
        cpa16(bKh + so, Khp + (size_t)tsm0 * 96 + go);
        cpa16(bKh + so + 16, Khp + (size_t)tsm0 * 96 + go + 8);
        cpa16(bKl + so, Klp + (size_t)tsm0 * 96 + go);
        cpa16(bKl + so + 16, Klp + (size_t)tsm0 * 96 + go + 8);
        cpcommit();
    };

    if (blockIdx.x < 2048) {
        issueT(blockIdx.x, 0, 0);
        issueT(blockIdx.x, 1, 1);
    }

    for (int tile = blockIdx.x; tile < 2048; tile += PGRID) {
        const int bg = tile >> 4;
        const int sn0 = ((tile >> 2) & 3) * 128, sm0 = (tile & 3) * 128;

        float c[4][4][4];
#pragma unroll
        for (int i = 0; i < 4; i++)
#pragma unroll
            for (int j = 0; j < 4; j++)
#pragma unroll
                for (int q = 0; q < 4; q++) c[i][j][q] = 0.f;

        for (int kt = 0; kt < 3; kt++) {
            cpwait<1>();
            __syncthreads();
            const unsigned aB = bQ + kt * ASTR + aOff;
            const unsigned kH = bKh + kt * ASTR + kOff;
            const unsigned kL = bKl + kt * ASTR + kOff;

#pragma unroll
            for (int k16 = 0; k16 < 2; k16++) {
                unsigned ah[4][4], f[4], bh[4][2], bl[4][2];
#pragma unroll
                for (int mf = 0; mf < 4; mf++)
                    ldsm4(ah[mf], aB + mf * 1280 + k16 * 32);
#pragma unroll
                for (int nf2 = 0; nf2 < 2; nf2++) {
                    ldsm4(f, kH + nf2 * 1280 + k16 * 32);
                    bh[nf2 * 2][0] = f[0]; bh[nf2 * 2][1] = f[2];
                    bh[nf2 * 2 + 1][0] = f[1]; bh[nf2 * 2 + 1][1] = f[3];
                    ldsm4(f, kL + nf2 * 1280 + k16 * 32);
                    bl[nf2 * 2][0] = f[0]; bl[nf2 * 2][1] = f[2];
                    bl[nf2 * 2 + 1][0] = f[1]; bl[nf2 * 2 + 1][1] = f[3];
                }
#pragma unroll
                for (int mf = 0; mf < 4; mf++)
#pragma unroll
                    for (int nf = 0; nf < 4; nf++) {
                        mmaf16(c[mf][nf], ah[mf], bh[nf][0], bh[nf][1]);
                        mmaf16(c[mf][nf], ah[mf], bl[nf][0], bl[nf][1]);
                    }
            }
            const int kn = kt + 2;
            if (kn < 3) issueT(tile, kn, kn); else cpcommit();
        }

        const int nt = tile + PGRID;
        if (nt < 2048) { issueT(nt, 0, 0); issueT(nt, 1, 1); }

        float s2 = sigma[bg & 7];
        s2 = s2 * s2;
#pragma unroll
        for (int mf = 0; mf < 4; mf++)
#pragma unroll
            for (int q2 = 0; q2 < 2; q2++) {
                const int n = sn0 + wm * 64 + mf * 16 + gid + q2 * 8;
#pragma unroll
                for (int nf = 0; nf < 4; nf++) {
                    const int m = sm0 + wn * 32 + nf * 8 + tig * 2;
                    const size_t idx = ((size_t)bg * Nn + n) * Nn + m;
                    float2 ev = *(const float2*)(eps + idx);
                    *(__half2*)(g_S + idx) = __halves2half2(
                        __float2half_rn(c[mf][nf][q2 * 2 + 0] + s2 * ev.x),
                        __float2half_rn(c[mf][nf][q2 * 2 + 1] + s2 * ev.y));
                }
            }
    }
}

// ---------------------------------------------------------------------------
// Mix via mma + mish + softmax (max-free).
// Per (b,n): T[16l x 512m] = P'[16l x 16k] . S[16k x 512m]  (k=g, 8..15 zero)
// 512 thr = 16 warps; warp w covers m in [w*32, w*32+32).
// S staged in smem rows 0..7 (cp.async), rows 8..15 zeroed; P' split 2-term.
// ---------------------------------------------------------------------------
#define SROW 520            // halfs per S smem row (1040B; 1040%128=16 -> conflict-free ldsm)

__global__ void __launch_bounds__(512, 2) mix_softmax_kernel(
    const float* __restrict__ encoding_bias)
{
    __shared__ __align__(16) __half sS[16 * SROW];
    __shared__ __align__(16) __half sP[2 * 16 * 40];   // 80B row stride per plane
    __shared__ float red[16][17];
    __shared__ float rsum[16];

    const int bn = blockIdx.x;
    const int b = bn >> 9, n = bn & 511;
    const int tid = threadIdx.x;
    const int lane = tid & 31, w = tid >> 5;
    const int gid = lane >> 2, tig = lane & 3;

    const unsigned sSb = sptr(sS), sPb = sptr(sP);

    // stage S rows 0..7, zero rows 8..15
    {
        const __half* Sp = g_S + ((size_t)(b * 8) * 512 + n) * 512;
        const int row = tid >> 6;            // 0..7
        const int colB = (tid & 63) * 16;    // 0..1008 bytes
        cpa16(sSb + row * 1040 + colB, Sp + (size_t)row * 262144 + colB / 2);
        *(uint4*)((char*)sS + (row + 8) * 1040 + colB) = make_uint4(0, 0, 0, 0);
    }
    // stage P' hi/lo: 2 planes x 16 rows x 32B
    if (tid < 64) {
        const int plane = tid >> 5, r = (tid >> 1) & 15, hw = tid & 1;
        const __half* src = (plane ? g_pl : g_ph) + r * 16 + hw * 8;
        cpa16(sPb + plane * 1280 + r * 80 + hw * 16, src);
    }
    cpcommit();
    cpwait<0>();
    __syncthreads();

    // fragments
    unsigned aPh[4], aPl[4];
    ldsm4(aPh, sPb + (lane & 15) * 80 + (lane >> 4) * 16);
    ldsm4(aPl, sPb + 1280 + (lane & 15) * 80 + (lane >> 4) * 16);

    unsigned bh[4][2], t0, t1, t2, t3;
    const unsigned bB = sSb + (lane & 15) * 1040 + (w * 32 + (lane >> 4) * 8) * 2;
    ldsm4t(t0, t1, t2, t3, bB);
    bh[0][0] = t0; bh[0][1] = t1; bh[1][0] = t2; bh[1][1] = t3;
    ldsm4t(t0, t1, t2, t3, bB + 32);
    bh[2][0] = t0; bh[2][1] = t1; bh[3][0] = t2; bh[3][1] = t3;

    float c[4][4];
#pragma unroll
    for (int nf = 0; nf < 4; nf++)
#pragma unroll
        for (int q = 0; q < 4; q++) c[nf][q] = 0.f;
#pragma unroll
    for (int nf = 0; nf < 4; nf++) {
        mmaf16(c[nf], aPh, bh[nf][0], bh[nf][1]);
        mmaf16(c[nf], aPl, bh[nf][0], bh[nf][1]);
    }

    // mish + exp (max-free; logits bounded ~|8|)
    const float scale = 0.03608439182435161f;
    const float* ebase = encoding_bias + (size_t)bn * 512 + w * 32 + tig * 2;
    float psum0 = 0.f, psum1 = 0.f;
#pragma unroll
    for (int nf = 0; nf < 4; nf++) {
        float2 bb = *(const float2*)(ebase + nf * 8);
#pragma unroll
        for (int j = 0; j < 4; j++) {
            float t = c[nf][j];
            float e = __expf(fminf(t, 15.f));
            float num = e * (e + 2.f);
            float mish = t * __fdividef(num, num + 2.f);
            float v = __expf(mish * scale + ((j & 1) ? bb.y : bb.x));
            c[nf][j] = v;
            if (j < 2) psum0 += v; else psum1 += v;
        }
    }

    // reduce: quad (same gid) -> smem across 16 warps
    psum0 += __shfl_xor_sync(0xffffffffu, psum0, 1);
    psum0 += __shfl_xor_sync(0xffffffffu, psum0, 2);
    psum1 += __shfl_xor_sync(0xffffffffu, psum1, 1);
    psum1 += __shfl_xor_sync(0xffffffffu, psum1, 2);
    if (tig == 0) {
        red[gid][w] = psum0;
        red[gid + 8][w] = psum1;
    }
    __syncthreads();
    {
        float v = (lane < 16) ? red[w][lane] : 0.f;
#pragma unroll
        for (int o = 8; o > 0; o >>= 1)
            v += __shfl_xor_sync(0xffffffffu, v, o);
        if (lane == 0) rsum[w] = v;
    }
    __syncthreads();

    const float ri0 = __fdividef(1.f, rsum[gid]);
    const float ri1 = __fdividef(1.f, rsum[gid + 8]);

    __half* A0 = g_Ah + (((size_t)(b * 16 + gid)) * 512 + n) * 512 + w * 32 + tig * 2;
    __half* A1 = g_Ah + (((size_t)(b * 16 + gid + 8)) * 512 + n) * 512 + w * 32 + tig * 2;
#pragma unroll
    for (int nf = 0; nf < 4; nf++) {
        *(__half2*)(A0 + nf * 8) = __halves2half2(
            __float2half_rn(c[nf][0] * ri0), __float2half_rn(c[nf][1] * ri0));
        *(__half2*)(A1 + nf * 8) = __halves2half2(
            __float2half_rn(c[nf][2] * ri1), __float2half_rn(c[nf][3] * ri1));
    }
}

// ---------------------------------------------------------------------------
// Persistent outv with cross-tile prefetch.  tiles = 4 x 256 = 1024, KT=16.
// ---------------------------------------------------------------------------
#define VSTR 6656          // 32 rows * 208B

__global__ void __launch_bounds__(256, 2) outv16()
{
    extern __shared__ char smem[];
    __half* sA = (__half*)smem;
    __half* sVh = (__half*)(smem + 3 * ASTR);

    const int tid = threadIdx.x;
    const int lane = tid & 31, warp = tid >> 5;
    const int wm = warp >> 2, wn = warp & 3;
    const int gid = lane >> 2, tig = lane & 3;

    const int aR = tid >> 1, aC = (tid & 1) * 16;
    const int vR = tid / 6, vC = (tid % 6) * 16;
    const bool vAct = tid < 192;
    const unsigned bA = sptr(sA), bVh = sptr(sVh);
    const unsigned aOff = (wm * 64 + (lane & 15)) * 80 + (lane >> 4) * 16;
    const unsigned vOff = (lane & 15) * 208 + (wn * 24 + (lane >> 4) * 8) * 2;
    const unsigned vOff2 = (lane & 15) * 208 + (wn * 24 + 16) * 2;

    auto issueT = [&](int t, int kt, int s) {
        const int tbl = t >> 2;
        const int tn0 = (t & 3) * 128;
        const __half* Ap = g_Ah + (size_t)tbl * Nn * Nn;
        const __half* Vhp = g_Vh + (size_t)tbl * Nn * Dd;
        const int k0 = kt << 5;
        unsigned sa = bA + s * ASTR + aR * 80 + aC * 2;
        const __half* ga = Ap + (size_t)(tn0 + aR) * 512 + k0 + aC;
        cpa16(sa, ga); cpa16(sa + 16, ga + 8);
        if (vAct) {
            unsigned sv = bVh + s * VSTR + vR * 208 + vC * 2;
            const __half* gv = Vhp + (size_t)(k0 + vR) * 96 + vC;
            cpa16(sv, gv); cpa16(sv + 16, gv + 8);
        }
        cpcommit();
    };

    if (blockIdx.x < 1024) {
        issueT(blockIdx.x, 0, 0);
        issueT(blockIdx.x, 1, 1);
    }

    for (int tile = blockIdx.x; tile < 1024; tile += PGRID) {
        const int bl = tile >> 2;
        const int n0 = (tile & 3) * 128;

        float c[4][3][4];
#pragma unroll
        for (int i = 0; i < 4; i++)
#pragma unroll
            for (int j = 0; j < 3; j++)
#pragma unroll
                for (int q = 0; q < 4; q++) c[i][j][q] = 0.f;

        for (int kt = 0; kt < 16; kt++) {
            cpwait<1>();
            __syncthreads();
            const int s = kt % 3;
            const unsigned aB = bA + s * ASTR + aOff;
            const unsigned vH = bVh + s * VSTR;

#pragma unroll
            for (int k16 = 0; k16 < 2; k16++) {
                unsigned ah[4][4], bh[3][2], t0, t1, t2, t3;
#pragma unroll
                for (int mf = 0; mf < 4; mf++)
                    ldsm4(ah[mf], aB + mf * 1280 + k16 * 32);
                ldsm4t(t0, t1, t2, t3, vH + vOff + k16 * 3328);
                bh[0][0] = t0; bh[0][1] = t1; bh[1][0] = t2; bh[1][1] = t3;
                ldsm2t(t0, t1, vH + vOff2 + k16 * 3328);
                bh[2][0] = t0; bh[2][1] = t1;

#pragma unroll
                for (int mf = 0; mf < 4; mf++)
#pragma unroll
                    for (int nf = 0; nf < 3; nf++)
                        mmaf16(c[mf][nf], ah[mf], bh[nf][0], bh[nf][1]);
            }
            const int kn = kt + 2;
            if (kn < 16) issueT(tile, kn, kn % 3); else cpcommit();
        }

        // KT=16: last chunk sat in stage 0 -> guard before reusing stages 0,1
        __syncthreads();
        const int nt = tile + PGRID;
        if (nt < 1024) { issueT(nt, 0, 0); issueT(nt, 1, 1); }

        const int b = bl >> 4, l = bl & 15;
#pragma unroll
        for (int mf = 0; mf < 4; mf++)
#pragma unroll
            for (int q2 = 0; q2 < 2; q2++) {
                const int n = n0 + wm * 64 + mf * 16 + gid + q2 * 8;
#pragma unroll
                for (int nf = 0; nf < 3; nf++) {
                    const int d = wn * 24 + nf * 8 + tig * 2;
                    const size_t idx = ((size_t)(b * 512 + n)) * 1536 + l * 96 + d;
                    *(__half2*)(g_Oh + idx) =
                        __halves2half2(__float2half_rn(c[mf][nf][q2 * 2 + 0]),
                                       __float2half_rn(c[mf][nf][q2 * 2 + 1]));
                }
            }
    }
}

// ---------------------------------------------------------------------------
extern "C" void kernel_launch(void* const* d_in, const int* in_sizes, int n_in,
                              void* d_out, int out_size)
{
    const float* x     = (const float*)d_in[0];
    const float* ebias = (const float*)d_in[1];
    const float* eps   = (const float*)d_in[2];
    const float* Wq    = (const float*)d_in[3];
    const float* Wk    = (const float*)d_in[4];
    const float* Wv    = (const float*)d_in[5];
    const float* bv    = (const float*)d_in[6];
    const float* sigma = (const float*)d_in[7];
    const float* p     = (const float*)d_in[8];
    const float* Wout  = (const float*)d_in[9];
    float* out = (float*)d_out;

    __half *xh, *wqkv, *woh, *qh, *kh, *kl, *vh, *oh;
    cudaGetSymbolAddress((void**)&xh,   g_xh);
    cudaGetSymbolAddress((void**)&wqkv, g_wqkv);
    cudaGetSymbolAddress((void**)&woh,  g_woh);
    cudaGetSymbolAddress((void**)&qh,   g_Qh);
    cudaGetSymbolAddress((void**)&kh,   g_Kh);
    cudaGetSymbolAddress((void**)&kl,   g_Kl);
    cudaGetSymbolAddress((void**)&vh,   g_Vh);
    cudaGetSymbolAddress((void**)&oh,   g_Oh);

    const int SM_1 = 3 * ASTR + 3 * BSTR;   // 56832
    const int SM_S = 9 * ASTR;              // 92160
    const int SM_O = 3 * ASTR + 3 * VSTR;   // 50688

    cudaFuncSetAttribute(gemm16<1>,
        cudaFuncAttributeMaxDynamicSharedMemorySize, SM_1);
    cudaFuncSetAttribute(gemm16<0>,
        cudaFuncAttributeMaxDynamicSharedMemorySize, SM_1);
    cudaFuncSetAttribute(scores16,
        cudaFuncAttributeMaxDynamicSharedMemorySize, SM_S);
    cudaFuncSetAttribute(outv16,
        cudaFuncAttributeMaxDynamicSharedMemorySize, SM_O);

    // fused input splits (x, Wq, Wk, Wv, Wout, p)
    splitAll<<<9601, 256>>>((const float4*)x, (const float4*)Wq,
                            (const float4*)Wk, (const float4*)Wv,
                            (const float4*)Wout, p);

    // merged Q+K+V projection: persistent, tiles 24x64
    gemm16<1><<<PGRID, 256, SM_1>>>(
        xh, wqkv, bv, qh, kh, kl, vh, nullptr, 768, 3072, 24, 1536);

    // scores: persistent, 2-term + sigma^2*eps -> fp16 S
    scores16<<<PGRID, 256, SM_S>>>(eps, sigma);

    // mix (mma) + mish + softmax (max-free) -> A fp16
    mix_softmax_kernel<<<Bb * Nn, 512>>>(ebias);

    // O = A @ V: persistent
    outv16<<<PGRID, 256, SM_O>>>();

    // out proj: persistent, tiles 6x64 -> fp32 d_out
    gemm16<0><<<PGRID, 256, SM_1>>>(
        oh, woh, nullptr, nullptr, nullptr, nullptr, nullptr, out, 1536, 768, 6, 384);
}

// round 17
// speedup vs baseline: 1.0505x; 1.0505x over previous
#include <cuda_runtime.h>
#include <cuda_fp16.h>
#include <math.h>

#define Bb 16
#define Nn 512
#define Dd 96
#define PGRID 592

// ---------------- scratch -------------------------------------------------
__device__ __half g_xh  [(size_t)8192 * 768];
__device__ __half g_wqkv[(size_t)768 * 3072];    // [k][ Wq | Wk | Wv ]
__device__ __half g_woh [(size_t)1536 * 768];
__device__ __half g_Qh[(size_t)128 * 512 * 96];
__device__ __half g_Kh[(size_t)128 * 512 * 96];
__device__ __half g_Vh[(size_t)256 * 512 * 96];
__device__ __half g_S [(size_t)128 * 512 * 512];
__device__ __half g_Ah[(size_t)256 * 512 * 512];
__device__ __half g_Oh[(size_t)8192 * 1536];

// ---------------- helpers --------------------------------------------------
__device__ __forceinline__ unsigned sptr(const void* p) {
    return (unsigned)__cvta_generic_to_shared(p);
}
__device__ __forceinline__ void cpa16(unsigned s, const void* g) {
    asm volatile("cp.async.cg.shared.global [%0], [%1], 16;" :: "r"(s), "l"(g));
}
__device__ __forceinline__ void cpcommit() {
    asm volatile("cp.async.commit_group;");
}
template<int W> __device__ __forceinline__ void cpwait() {
    asm volatile("cp.async.wait_group %0;" :: "n"(W));
}
__device__ __forceinline__ void ldsm4(unsigned f[4], unsigned a) {
    asm volatile("ldmatrix.sync.aligned.m8n8.x4.shared.b16 {%0,%1,%2,%3}, [%4];"
                 : "=r"(f[0]), "=r"(f[1]), "=r"(f[2]), "=r"(f[3]) : "r"(a));
}
__device__ __forceinline__ void ldsm4t(unsigned& r0, unsigned& r1, unsigned& r2,
                                       unsigned& r3, unsigned a) {
    asm volatile("ldmatrix.sync.aligned.m8n8.x4.trans.shared.b16 {%0,%1,%2,%3}, [%4];"
                 : "=r"(r0), "=r"(r1), "=r"(r2), "=r"(r3) : "r"(a));
}
__device__ __forceinline__ void ldsm2t(unsigned& r0, unsigned& r1, unsigned a) {
    asm volatile("ldmatrix.sync.aligned.m8n8.x2.trans.shared.b16 {%0,%1}, [%2];"
                 : "=r"(r0), "=r"(r1) : "r"(a));
}
__device__ __forceinline__ void mmaf16(float c[4], const unsigned a[4],
                                       unsigned b0, unsigned b1) {
    asm volatile(
        "mma.sync.aligned.m16n8k16.row.col.f32.f16.f16.f32 "
        "{%0,%1,%2,%3}, {%4,%5,%6,%7}, {%8,%9}, {%0,%1,%2,%3};"
        : "+f"(c[0]), "+f"(c[1]), "+f"(c[2]), "+f"(c[3])
        : "r"(a[0]), "r"(a[1]), "r"(a[2]), "r"(a[3]), "r"(b0), "r"(b1));
}

// ---------------- fused input split (x, Wq, Wk, Wv, Wout in one launch) ----
__global__ void __launch_bounds__(256) splitAll(
    const float4* __restrict__ x, const float4* __restrict__ Wq,
    const float4* __restrict__ Wk, const float4* __restrict__ Wv,
    const float4* __restrict__ Wout)
{
    int i = blockIdx.x * 256 + threadIdx.x;
    if (i < 1572864) {
        float4 v = x[i];
        ((__half2*)g_xh)[i * 2]     = __halves2half2(__float2half_rn(v.x), __float2half_rn(v.y));
        ((__half2*)g_xh)[i * 2 + 1] = __halves2half2(__float2half_rn(v.z), __float2half_rn(v.w));
    } else if (i < 1720320) {
        int j = i - 1572864;
        int row = j / 192, col = (j % 192) * 4;
        float4 v = Wq[j];
        __half2* d = (__half2*)(g_wqkv + (size_t)row * 3072 + col);
        d[0] = __halves2half2(__float2half_rn(v.x), __float2half_rn(v.y));
        d[1] = __halves2half2(__float2half_rn(v.z), __float2half_rn(v.w));
    } else if (i < 1867776) {
        int j = i - 1720320;
        int row = j / 192, col = (j % 192) * 4;
        float4 v = Wk[j];
        __half2* d = (__half2*)(g_wqkv + (size_t)row * 3072 + 768 + col);
        d[0] = __halves2half2(__float2half_rn(v.x), __float2half_rn(v.y));
        d[1] = __halves2half2(__float2half_rn(v.z), __float2half_rn(v.w));
    } else if (i < 2162688) {
        int j = i - 1867776;
        int row = j / 384, col = (j % 384) * 4;
        float4 v = Wv[j];
        __half2* d = (__half2*)(g_wqkv + (size_t)row * 3072 + 1536 + col);
        d[0] = __halves2half2(__float2half_rn(v.x), __float2half_rn(v.y));
        d[1] = __halves2half2(__float2half_rn(v.z), __float2half_rn(v.w));
    } else if (i < 2457600) {
        int j = i - 2162688;
        float4 v = Wout[j];
        ((__half2*)g_woh)[j * 2]     = __halves2half2(__float2half_rn(v.x), __float2half_rn(v.y));
        ((__half2*)g_woh)[j * 2 + 1] = __halves2half2(__float2half_rn(v.z), __float2half_rn(v.w));
    }
}

// ---------------------------------------------------------------------------
// Persistent GEMM with cross-tile prefetch. BM=128 BN=128 BK=32, 3 stages.
// MODE 0: fp32 rowmajor (outF).  MODE 1: QKV merged epilogue (all single fp16).
// ---------------------------------------------------------------------------
#define ASTR 10240          // 128 rows * 80B
#define BSTR 8704           // 32 rows * 272B

template<int MODE>
__global__ void __launch_bounds__(256, 2) gemm16(
    const __half* __restrict__ Agh, const __half* __restrict__ Bgh,
    const float* __restrict__ bias,
    __half* __restrict__ o0, __half* __restrict__ o1, __half* __restrict__ o3,
    float* __restrict__ outF, int K, int N, int tilesX, int nTiles)
{
    extern __shared__ char smem[];
    __half* sA = (__half*)smem;
    __half* sBh = (__half*)(smem + 3 * ASTR);

    const int tid = threadIdx.x;
    const int lane = tid & 31, warp = tid >> 5;
    const int wm = warp >> 2, wn = warp & 3;
    const int gid = lane >> 2, tig = lane & 3;

    const int aR = tid >> 1, aC = (tid & 1) * 16;
    const int bR = tid >> 3, bC = (tid & 7) * 16;
    const unsigned sAb = sptr(sA), sBhb = sptr(sBh);
    const unsigned aOff = (wm * 64 + (lane & 15)) * 80 + (lane >> 4) * 16;
    const unsigned bOff = (lane & 15) * 272 + (wn * 32 + (lane >> 4) * 8) * 2;
    const int KT = K >> 5;

    auto issueT = [&](int t, int kt, int s) {
        const int tm0 = (t / tilesX) * 128;
        const int tn0 = (t % tilesX) * 128;
        const int k0 = kt << 5;
        const __half* ga = Agh + (size_t)(tm0 + aR) * K + k0 + aC;
        unsigned sa = sAb + s * ASTR + aR * 80 + aC * 2;
        cpa16(sa, ga); cpa16(sa + 16, ga + 8);
        const __half* gb = Bgh + (size_t)(k0 + bR) * N + tn0 + bC;
        unsigned sb = sBhb + s * BSTR + bR * 272 + bC * 2;
        cpa16(sb, gb); cpa16(sb + 16, gb + 8);
        cpcommit();
    };

    if (blockIdx.x < nTiles) {
        issueT(blockIdx.x, 0, 0);
        issueT(blockIdx.x, 1, 1);
    }

    for (int tile = blockIdx.x; tile < nTiles; tile += PGRID) {
        const int m0 = (tile / tilesX) * 128;
        const int n0 = (tile % tilesX) * 128;

        float c[4][4][4];
#pragma unroll
        for (int i = 0; i < 4; i++)
#pragma unroll
            for (int j = 0; j < 4; j++)
#pragma unroll
                for (int q = 0; q < 4; q++) c[i][j][q] = 0.f;

        for (int kt = 0; kt < KT; kt++) {
            cpwait<1>();
            __syncthreads();
            const int s = kt % 3;
            const unsigned aB = sAb + s * ASTR + aOff;
            const unsigned bB = sBhb + s * BSTR + bOff;

#pragma unroll
            for (int k16 = 0; k16 < 2; k16++) {
                unsigned ah[4][4], bh[4][2], t0, t1, t2, t3;
#pragma unroll
                for (int mf = 0; mf < 4; mf++)
                    ldsm4(ah[mf], aB + mf * 1280 + k16 * 32);
#pragma unroll
                for (int nf2 = 0; nf2 < 2; nf2++) {
                    ldsm4t(t0, t1, t2, t3, bB + k16 * 4352 + nf2 * 32);
                    bh[nf2 * 2][0] = t0; bh[nf2 * 2][1] = t1;
                    bh[nf2 * 2 + 1][0] = t2; bh[nf2 * 2 + 1][1] = t3;
                }
#pragma unroll
                for (int mf = 0; mf < 4; mf++)
#pragma unroll
                    for (int nf = 0; nf < 4; nf++)
                        mmaf16(c[mf][nf], ah[mf], bh[nf][0], bh[nf][1]);
            }
            const int kn = kt + 2;
            if (kn < KT) issueT(tile, kn, kn % 3); else cpcommit();
        }

        const int nt = tile + PGRID;
        if (nt < nTiles) { issueT(nt, 0, 0); issueT(nt, 1, 1); }

#pragma unroll
        for (int mf = 0; mf < 4; mf++)
#pragma unroll
            for (int q2 = 0; q2 < 2; q2++) {
                const int row = m0 + wm * 64 + mf * 16 + gid + q2 * 8;
                const int b = row >> 9, n = row & 511;
#pragma unroll
                for (int nf = 0; nf < 4; nf++) {
                    const int col = n0 + wn * 32 + nf * 8 + tig * 2;
                    float v0 = c[mf][nf][q2 * 2 + 0];
                    float v1 = c[mf][nf][q2 * 2 + 1];
                    if (MODE == 0) {
                        *(float2*)(outF + (size_t)row * N + col) = make_float2(v0, v1);
                    } else {
                        if (col < 768) {
                            const int h = col / 96, d = col - h * 96;
                            const size_t idx = (((size_t)(b * 8 + h)) * 512 + n) * 96 + d;
                            *(__half2*)(o0 + idx) =
                                __halves2half2(__float2half_rn(v0), __float2half_rn(v1));
                        } else if (col < 1536) {
                            const int cc = col - 768;
                            const int h = cc / 96, d = cc - h * 96;
                            const size_t idx = (((size_t)(b * 8 + h)) * 512 + n) * 96 + d;
                            *(__half2*)(o1 + idx) =
                                __halves2half2(__float2half_rn(v0), __float2half_rn(v1));
                        } else {
                            const int cc = col - 1536;
                            const int h = cc / 96, d = cc - h * 96;
                            v0 += bias[cc]; v1 += bias[cc + 1];
                            const size_t idx = (((size_t)(b * 16 + h)) * 512 + n) * 96 + d;
                            *(__half2*)(o3 + idx) =
                                __halves2half2(__float2half_rn(v0), __float2half_rn(v1));
                        }
                    }
                }
            }
    }
}

// ---------------------------------------------------------------------------
// Persistent scores, 1-term (Q,K single fp16) + sigma^2*eps -> fp16 S.
// tiles: 128 bg x 4 x 4 = 2048, KT=3.
// ---------------------------------------------------------------------------
__global__ void __launch_bounds__(256, 2) scores16(
    const float* __restrict__ eps, const float* __restrict__ sigma)
{
    extern __shared__ char smem[];
    __half* sQ  = (__half*)smem;
    __half* sKh = (__half*)(smem + 3 * ASTR);

    const int tid = threadIdx.x;
    const int lane = tid & 31, warp = tid >> 5;
    const int wm = warp >> 2, wn = warp & 3;
    const int gid = lane >> 2, tig = lane & 3;

    const int aR = tid >> 1, aC = (tid & 1) * 16;
    const unsigned bQ = sptr(sQ), bKh = sptr(sKh);
    const unsigned aOff = (wm * 64 + (lane & 15)) * 80 + (lane >> 4) * 16;
    const unsigned kOff = (wn * 32 + (lane & 15)) * 80 + (lane >> 4) * 16;

    auto issueT = [&](int t, int kt, int s) {
        const int tbg = t >> 4;
        const int tsn0 = ((t >> 2) & 3) * 128, tsm0 = (t & 3) * 128;
        const __half* Qp  = g_Qh + (size_t)tbg * Nn * Dd;
        const __half* Khp = g_Kh + (size_t)tbg * Nn * Dd;
        const int k0 = kt << 5;
        unsigned so = s * ASTR + aR * 80 + aC * 2;
        size_t go = (size_t)aR * 96 + k0 + aC;
        cpa16(bQ + so, Qp + (size_t)tsn0 * 96 + go);
        cpa16(bQ + so + 16, Qp + (size_t)tsn0 * 96 + go + 8);
        cpa16(bKh + so, Khp + (size_t)tsm0 * 96 + go);
        cpa16(bKh + so + 16, Khp + (size_t)tsm0 * 96 + go + 8);
        cpcommit();
    };

    if (blockIdx.x < 2048) {
        issueT(blockIdx.x, 0, 0);
        issueT(blockIdx.x, 1, 1);
    }

    for (int tile = blockIdx.x; tile < 2048; tile += PGRID) {
        const int bg = tile >> 4;
        const int sn0 = ((tile >> 2) & 3) * 128, sm0 = (tile & 3) * 128;

        float c[4][4][4];
#pragma unroll
        for (int i = 0; i < 4; i++)
#pragma unroll
            for (int j = 0; j < 4; j++)
#pragma unroll
                for (int q = 0; q < 4; q++) c[i][j][q] = 0.f;

        for (int kt = 0; kt < 3; kt++) {
            cpwait<1>();
            __syncthreads();
            const unsigned aB = bQ + kt * ASTR + aOff;
            const unsigned kH = bKh + kt * ASTR + kOff;

#pragma unroll
            for (int k16 = 0; k16 < 2; k16++) {
                unsigned ah[4][4], f[4], bh[4][2];
#pragma unroll
                for (int mf = 0; mf < 4; mf++)
                    ldsm4(ah[mf], aB + mf * 1280 + k16 * 32);
#pragma unroll
                for (int nf2 = 0; nf2 < 2; nf2++) {
                    ldsm4(f, kH + nf2 * 1280 + k16 * 32);
                    bh[nf2 * 2][0] = f[0]; bh[nf2 * 2][1] = f[2];
                    bh[nf2 * 2 + 1][0] = f[1]; bh[nf2 * 2 + 1][1] = f[3];
                }
#pragma unroll
                for (int mf = 0; mf < 4; mf++)
#pragma unroll
                    for (int nf = 0; nf < 4; nf++)
                        mmaf16(c[mf][nf], ah[mf], bh[nf][0], bh[nf][1]);
            }
            const int kn = kt + 2;
            if (kn < 3) issueT(tile, kn, kn); else cpcommit();
        }

        const int nt = tile + PGRID;
        if (nt < 2048) { issueT(nt, 0, 0); issueT(nt, 1, 1); }

        float s2 = sigma[bg & 7];
        s2 = s2 * s2;
#pragma unroll
        for (int mf = 0; mf < 4; mf++)
#pragma unroll
            for (int q2 = 0; q2 < 2; q2++) {
                const int n = sn0 + wm * 64 + mf * 16 + gid + q2 * 8;
#pragma unroll
                for (int nf = 0; nf < 4; nf++) {
                    const int m = sm0 + wn * 32 + nf * 8 + tig * 2;
                    const size_t idx = ((size_t)bg * Nn + n) * Nn + m;
                    float2 ev = *(const float2*)(eps + idx);
                    *(__half2*)(g_S + idx) = __halves2half2(
                        __float2half_rn(c[mf][nf][q2 * 2 + 0] + s2 * ev.x),
                        __float2half_rn(c[mf][nf][q2 * 2 + 1] + s2 * ev.y));
                }
            }
    }
}

// ---------------------------------------------------------------------------
// Mix + mish + softmax (max-free), transposed: warp = l, lane x16 = m.
// 256-thread blocks, grid (8192, 2): l = blockIdx.y*8 + warp.
// ---------------------------------------------------------------------------
__global__ void __launch_bounds__(256, 4) mix_softmax_kernel(
    const float* __restrict__ encoding_bias, const float* __restrict__ p)
{
    const int bn = blockIdx.x;
    const int b = bn >> 9, n = bn & 511;
    const int tid = threadIdx.x;
    const int lane = tid & 31, l = blockIdx.y * 8 + (tid >> 5);

    float pr[8];
#pragma unroll
    for (int g = 0; g < 8; g++) pr[g] = __ldg(p + g * 16 + l);

    const float scale = 0.03608439182435161f;
    const __half* Sbase = g_S + (((size_t)(b * 8)) * 512 + n) * 512;
    const float* ebase = encoding_bias + ((size_t)bn) * 512;

    float vals[16];
    float psum = 0.f;

#pragma unroll
    for (int ib = 0; ib < 2; ib++) {
        const int m8 = (lane + ib * 32) * 8;

        float tacc[8];
#pragma unroll
        for (int j = 0; j < 8; j++) tacc[j] = 0.f;

#pragma unroll
        for (int g = 0; g < 8; g++) {
            uint4 sv = *(const uint4*)(Sbase + (size_t)g * (512 * 512) + m8);
            const __half2* h2 = (const __half2*)&sv;
#pragma unroll
            for (int j2 = 0; j2 < 4; j2++) {
                float2 f = __half22float2(h2[j2]);
                tacc[j2 * 2 + 0] = fmaf(f.x, pr[g], tacc[j2 * 2 + 0]);
                tacc[j2 * 2 + 1] = fmaf(f.y, pr[g], tacc[j2 * 2 + 1]);
            }
        }

        float4 bv0 = *(const float4*)(ebase + m8);
        float4 bv1 = *(const float4*)(ebase + m8 + 4);
        float bb[8] = {bv0.x, bv0.y, bv0.z, bv0.w, bv1.x, bv1.y, bv1.z, bv1.w};

#pragma unroll
        for (int j = 0; j < 8; j++) {
            float t = tacc[j];
            float e = __expf(fminf(t, 15.f));
            float num = e * (e + 2.f);
            float mish = t * __fdividef(num, num + 2.f);
            float v = __expf(mish * scale + bb[j]);   // logits bounded ~|8|
            vals[ib * 8 + j] = v;
            psum += v;
        }
    }

#pragma unroll
    for (int o = 16; o > 0; o >>= 1)
        psum += __shfl_xor_sync(0xffffffffu, psum, o);
    const float rinv = __fdividef(1.f, psum);

    __half* Abase = g_Ah + (((size_t)(b * 16 + l)) * 512 + n) * 512;
#pragma unroll
    for (int ib = 0; ib < 2; ib++) {
        const int m8 = (lane + ib * 32) * 8;
        uint4 pk;
        unsigned* pku = (unsigned*)&pk;
#pragma unroll
        for (int j2 = 0; j2 < 4; j2++) {
            __half2 h = __halves2half2(
                __float2half_rn(vals[ib * 8 + j2 * 2 + 0] * rinv),
                __float2half_rn(vals[ib * 8 + j2 * 2 + 1] * rinv));
            pku[j2] = *(unsigned*)&h;
        }
        *(uint4*)(Abase + m8) = pk;
    }
}

// ---------------------------------------------------------------------------
// Persistent outv with cross-tile prefetch.  tiles = 4 x 256 = 1024, KT=16.
// ---------------------------------------------------------------------------
#define VSTR 6656          // 32 rows * 208B

__global__ void __launch_bounds__(256, 2) outv16()
{
    extern __shared__ char smem[];
    __half* sA = (__half*)smem;
    __half* sVh = (__half*)(smem + 3 * ASTR);

    const int tid = threadIdx.x;
    const int lane = tid & 31, warp = tid >> 5;
    const int wm = warp >> 2, wn = warp & 3;
    const int gid = lane >> 2, tig = lane & 3;

    const int aR = tid >> 1, aC = (tid & 1) * 16;
    const int vR = tid / 6, vC = (tid % 6) * 16;
    const bool vAct = tid < 192;
    const unsigned bA = sptr(sA), bVh = sptr(sVh);
    const unsigned aOff = (wm * 64 + (lane & 15)) * 80 + (lane >> 4) * 16;
    const unsigned vOff = (lane & 15) * 208 + (wn * 24 + (lane >> 4) * 8) * 2;
    const unsigned vOff2 = (lane & 15) * 208 + (wn * 24 + 16) * 2;

    auto issueT = [&](int t, int kt, int s) {
        const int tbl = t >> 2;
        const int tn0 = (t & 3) * 128;
        const __half* Ap = g_Ah + (size_t)tbl * Nn * Nn;
        const __half* Vhp = g_Vh + (size_t)tbl * Nn * Dd;
        const int k0 = kt << 5;
        unsigned sa = bA + s * ASTR + aR * 80 + aC * 2;
        const __half* ga = Ap + (size_t)(tn0 + aR) * 512 + k0 + aC;
        cpa16(sa, ga); cpa16(sa + 16, ga + 8);
        if (vAct) {
            unsigned sv = bVh + s * VSTR + vR * 208 + vC * 2;
            const __half* gv = Vhp + (size_t)(k0 + vR) * 96 + vC;
            cpa16(sv, gv); cpa16(sv + 16, gv + 8);
        }
        cpcommit();
    };

    if (blockIdx.x < 1024) {
        issueT(blockIdx.x, 0, 0);
        issueT(blockIdx.x, 1, 1);
    }

    for (int tile = blockIdx.x; tile < 1024; tile += PGRID) {
        const int bl = tile >> 2;
        const int n0 = (tile & 3) * 128;

        float c[4][3][4];
#pragma unroll
        for (int i = 0; i < 4; i++)
#pragma unroll
            for (int j = 0; j < 3; j++)
#pragma unroll
                for (int q = 0; q < 4; q++) c[i][j][q] = 0.f;

        for (int kt = 0; kt < 16; kt++) {
            cpwait<1>();
            __syncthreads();
            const int s = kt % 3;
            const unsigned aB = bA + s * ASTR + aOff;
            const unsigned vH = bVh + s * VSTR;

#pragma unroll
            for (int k16 = 0; k16 < 2; k16++) {
                unsigned ah[4][4], bh[3][2], t0, t1, t2, t3;
#pragma unroll
                for (int mf = 0; mf < 4; mf++)
                    ldsm4(ah[mf], aB + mf * 1280 + k16 * 32);
                ldsm4t(t0, t1, t2, t3, vH + vOff + k16 * 3328);
                bh[0][0] = t0; bh[0][1] = t1; bh[1][0] = t2; bh[1][1] = t3;
                ldsm2t(t0, t1, vH + vOff2 + k16 * 3328);
                bh[2][0] = t0; bh[2][1] = t1;

#pragma unroll
                for (int mf = 0; mf < 4; mf++)
#pragma unroll
                    for (int nf = 0; nf < 3; nf++)
                        mmaf16(c[mf][nf], ah[mf], bh[nf][0], bh[nf][1]);
            }
            const int kn = kt + 2;
            if (kn < 16) issueT(tile, kn, kn % 3); else cpcommit();
        }

        // KT=16: last chunk sat in stage 0 -> guard before reusing stages 0,1
        __syncthreads();
        const int nt = tile + PGRID;
        if (nt < 1024) { issueT(nt, 0, 0); issueT(nt, 1, 1); }

        const int b = bl >> 4, l = bl & 15;
#pragma unroll
        for (int mf = 0; mf < 4; mf++)
#pragma unroll
            for (int q2 = 0; q2 < 2; q2++) {
                const int n = n0 + wm * 64 + mf * 16 + gid + q2 * 8;
#pragma unroll
                for (int nf = 0; nf < 3; nf++) {
                    const int d = wn * 24 + nf * 8 + tig * 2;
                    const size_t idx = ((size_t)(b * 512 + n)) * 1536 + l * 96 + d;
                    *(__half2*)(g_Oh + idx) =
                        __halves2half2(__float2half_rn(c[mf][nf][q2 * 2 + 0]),
                                       __float2half_rn(c[mf][nf][q2 * 2 + 1]));
                }
            }
    }
}

// ---------------------------------------------------------------------------
extern "C" void kernel_launch(void* const* d_in, const int* in_sizes, int n_in,
                              void* d_out, int out_size)
{
    const float* x     = (const float*)d_in[0];
    const float* ebias = (const float*)d_in[1];
    const float* eps   = (const float*)d_in[2];
    const float* Wq    = (const float*)d_in[3];
    const float* Wk    = (const float*)d_in[4];
    const float* Wv    = (const float*)d_in[5];
    const float* bv    = (const float*)d_in[6];
    const float* sigma = (const float*)d_in[7];
    const float* p     = (const float*)d_in[8];
    const float* Wout  = (const float*)d_in[9];
    float* out = (float*)d_out;

    __half *xh, *wqkv, *woh, *qh, *kh, *vh, *oh;
    cudaGetSymbolAddress((void**)&xh,   g_xh);
    cudaGetSymbolAddress((void**)&wqkv, g_wqkv);
    cudaGetSymbolAddress((void**)&woh,  g_woh);
    cudaGetSymbolAddress((void**)&qh,   g_Qh);
    cudaGetSymbolAddress((void**)&kh,   g_Kh);
    cudaGetSymbolAddress((void**)&vh,   g_Vh);
    cudaGetSymbolAddress((void**)&oh,   g_Oh);

    const int SM_1 = 3 * ASTR + 3 * BSTR;   // 56832
    const int SM_S = 6 * ASTR;              // 61440
    const int SM_O = 3 * ASTR + 3 * VSTR;   // 50688

    cudaFuncSetAttribute(gemm16<1>,
        cudaFuncAttributeMaxDynamicSharedMemorySize, SM_1);
    cudaFuncSetAttribute(gemm16<0>,
        cudaFuncAttributeMaxDynamicSharedMemorySize, SM_1);
    cudaFuncSetAttribute(scores16,
        cudaFuncAttributeMaxDynamicSharedMemorySize, SM_S);
    cudaFuncSetAttribute(outv16,
        cudaFuncAttributeMaxDynamicSharedMemorySize, SM_O);

    // fused input splits (x, Wq, Wk, Wv, Wout)
    splitAll<<<9600, 256>>>((const float4*)x, (const float4*)Wq,
                            (const float4*)Wk, (const float4*)Wv,
                            (const float4*)Wout);

    // merged Q+K+V projection: persistent, tiles 24x64 (all single stores)
    gemm16<1><<<PGRID, 256, SM_1>>>(
        xh, wqkv, bv, qh, kh, vh, nullptr, 768, 3072, 24, 1536);

    // scores: persistent, 1-term + sigma^2*eps -> fp16 S
    scores16<<<PGRID, 256, SM_S>>>(eps, sigma);

    // mix + mish + softmax (max-free, transposed, 256-thr blocks) -> A fp16
    mix_softmax_kernel<<<dim3(Bb * Nn, 2), 256>>>(ebias, p);

    // O = A @ V: persistent
    outv16<<<PGRID, 256, SM_O>>>();

    // out proj: persistent, tiles 6x64 -> fp32 d_out
    gemm16<0><<<PGRID, 256, SM_1>>>(
        oh, woh, nullptr, nullptr, nullptr, nullptr, out, 1536, 768, 6, 384);
}